// round 14
// baseline (speedup 1.0000x reference)
#include <cuda_runtime.h>
#include <cuda_bf16.h>
#include <math.h>
#include <stdint.h>

// Problem constants
#define Tt 200
#define Bb 512
#define Cc 128
#define Hh 4
#define Kk 5
#define Ff 512
#define Ll 2
#define BTt (Tt*Bb)        // 102400 tokens
#define HK  (Hh*Kk)        // 20
#define NPART (BTt/8)

// Scratch (activations stored bf16; all math fp32)
__device__ __nv_bfloat16 g_XLN [BTt*Cc];
__device__ __nv_bfloat16 g_XLN2[BTt*Cc];
__device__ uint8_t g_XLN8[BTt*Cc];
__device__ uint8_t g_WT1 [Ll*Ff*Cc];
__device__ uint8_t g_WT2 [Ll*Cc*Ff];
__device__ float g_pL [NPART];
__device__ float g_pM [NPART];

// ---------------------------------------------------------------------------
__device__ __forceinline__ uint32_t smem_to_u32(const void* p) {
    uint32_t a;
    asm("{ .reg .u64 t; cvta.to.shared.u64 t, %1; cvt.u32.u64 %0, t; }" : "=r"(a) : "l"(p));
    return a;
}
__device__ __forceinline__ uint16_t f2e4m3x2(float lo, float hi) {
    uint16_t r;
    asm("cvt.rn.satfinite.e4m3x2.f32 %0, %1, %2;" : "=h"(r) : "f"(hi), "f"(lo));
    return r;
}
__device__ __forceinline__ void mma_fp8(float* c, const uint32_t* a, const uint32_t* b) {
    asm volatile(
        "mma.sync.aligned.m16n8k32.row.col.f32.e4m3.e4m3.f32 "
        "{%0,%1,%2,%3}, {%4,%5,%6,%7}, {%8,%9}, {%0,%1,%2,%3};\n"
        : "+f"(c[0]), "+f"(c[1]), "+f"(c[2]), "+f"(c[3])
        : "r"(a[0]), "r"(a[1]), "r"(a[2]), "r"(a[3]), "r"(b[0]), "r"(b[1]));
}
__device__ __forceinline__ void ldsm4(uint32_t* r, uint32_t addr) {
    asm volatile("ldmatrix.sync.aligned.m8n8.x4.shared.b16 {%0,%1,%2,%3}, [%4];"
        : "=r"(r[0]), "=r"(r[1]), "=r"(r[2]), "=r"(r[3]) : "r"(addr));
}
__device__ __forceinline__ void cp16(uint32_t dst, const void* src) {
    asm volatile("cp.async.cg.shared.global [%0], [%1], 16;" :: "r"(dst), "l"(src));
}
#define CP_COMMIT() asm volatile("cp.async.commit_group;" ::: "memory")
#define CP_WAIT0()  asm volatile("cp.async.wait_group 0;" ::: "memory")
#define CP_WAIT2()  asm volatile("cp.async.wait_group 2;" ::: "memory")

// bf16x4 <-> float4 helpers
__device__ __forceinline__ float4 ldbf4(const __nv_bfloat16* p) {
    uint2 u = *(const uint2*)p;
    __nv_bfloat162 a = *reinterpret_cast<__nv_bfloat162*>(&u.x);
    __nv_bfloat162 b = *reinterpret_cast<__nv_bfloat162*>(&u.y);
    return make_float4(__low2float(a), __high2float(a),
                       __low2float(b), __high2float(b));
}
__device__ __forceinline__ void stbf4(__nv_bfloat16* p, float4 v) {
    __nv_bfloat162 a = __floats2bfloat162_rn(v.x, v.y);
    __nv_bfloat162 b = __floats2bfloat162_rn(v.z, v.w);
    uint2 u;
    u.x = *(uint32_t*)&a; u.y = *(uint32_t*)&b;
    *(uint2*)p = u;
}

// warp-row LayerNorm (32-lane row of float4)
__device__ __forceinline__ float4 warp_ln(float4 v, const float* __restrict__ g,
                                          const float* __restrict__ beta, int lane)
{
    float s = v.x + v.y + v.z + v.w;
    #pragma unroll
    for (int o = 16; o; o >>= 1) s += __shfl_xor_sync(0xffffffffu, s, o);
    float mean = s * (1.0f / Cc);
    float dx = v.x - mean, dy = v.y - mean, dz = v.z - mean, dw = v.w - mean;
    float q = dx*dx + dy*dy + dz*dz + dw*dw;
    #pragma unroll
    for (int o = 16; o; o >>= 1) q += __shfl_xor_sync(0xffffffffu, q, o);
    float rstd = rsqrtf(q * (1.0f / Cc) + 1e-5f);
    float4 gv = ((const float4*)g)[lane];
    float4 bv = ((const float4*)beta)[lane];
    float4 r;
    r.x = dx * rstd * gv.x + bv.x;
    r.y = dy * rstd * gv.y + bv.y;
    r.z = dz * rstd * gv.z + bv.z;
    r.w = dw * rstd * gv.w + bv.w;
    return r;
}

// ---------------------------------------------------------------------------
__global__ void embed_ln_kernel(const float* __restrict__ emb,
                                const int* __restrict__ seq,
                                const float* __restrict__ sg,
                                const float* __restrict__ sb,
                                __nv_bfloat16* __restrict__ XLN)
{
    int warp = threadIdx.x >> 5, lane = threadIdx.x & 31;
    int p = blockIdx.x * 8 + warp;
    int t = p / Bb, b = p - t * Bb;
    int id = seq[b * Tt + t];
    float4 v = ((const float4*)(emb + (size_t)id * Cc))[lane];
    float4 r = warp_ln(v, sg, sb, lane);
    stbf4(XLN + (size_t)p * Cc + lane * 4, r);
}

// ---------------------------------------------------------------------------
// Dynamic conv + per-layer LN, sliding-window version (converged)
// ---------------------------------------------------------------------------
__global__ void conv_ln_kernel(const __nv_bfloat16* __restrict__ XLN,
                               const float* __restrict__ cw,
                               const float* __restrict__ cb,
                               const float* __restrict__ lng,
                               const float* __restrict__ lnb,
                               __nv_bfloat16* __restrict__ XLN2,
                               uint8_t* __restrict__ XLN8)
{
    __shared__ float  ws[Cc * HK];
    __shared__ float4 xs[8][32];
    __shared__ float  lg[8][HK];
    __shared__ float  wt[8][HK];

    const int tid = threadIdx.x, warp = tid >> 5, lane = tid & 31;
    const int t0 = blockIdx.x * 8;
    const int b  = blockIdx.y * 8 + warp;
    const int h  = lane >> 3;

    #pragma unroll
    for (int i = 0; i < (Cc * HK) / 256; i++)
        ws[i * 256 + tid] = cw[i * 256 + tid];
    __syncthreads();

    float4 win[Kk - 1];
    #pragma unroll
    for (int k = 0; k < Kk - 1; k++) {
        int ts = t0 - (Kk - 1) + k;
        win[k] = (ts >= 0)
            ? ldbf4(XLN + ((size_t)ts * Bb + b) * Cc + lane * 4)
            : make_float4(0.f, 0.f, 0.f, 0.f);
    }

    for (int it = 0; it < 8; it++) {
        const int t = t0 + it;
        const size_t p = (size_t)t * Bb + b;
        float4 xv = ldbf4(XLN + p * Cc + lane * 4);
        xs[warp][lane] = xv;
        __syncwarp();

        float e = 0.0f;
        if (lane < HK) {
            float acc = __ldg(cb + lane);
            #pragma unroll 8
            for (int c4 = 0; c4 < 32; c4++) {
                float4 xq = xs[warp][c4];
                const float* wr = &ws[c4 * 4 * HK + lane];
                acc += xq.x * wr[0] + xq.y * wr[HK]
                     + xq.z * wr[2 * HK] + xq.w * wr[3 * HK];
            }
            lg[warp][lane] = acc;
        }
        __syncwarp();
        if (lane < HK) {
            int hb = (lane / Kk) * Kk;
            float m = lg[warp][hb];
            #pragma unroll
            for (int k = 1; k < Kk; k++) m = fmaxf(m, lg[warp][hb + k]);
            e = expf(lg[warp][lane] - m);
            wt[warp][lane] = e;
        }
        __syncwarp();
        float sden = 0.0f;
        if (lane < HK) {
            int hb = (lane / Kk) * Kk;
            #pragma unroll
            for (int k = 0; k < Kk; k++) sden += wt[warp][hb + k];
        }
        __syncwarp();
        if (lane < HK) wt[warp][lane] = e / sden;
        __syncwarp();

        float w4[Kk];
        #pragma unroll
        for (int k = 0; k < Kk; k++) w4[k] = wt[warp][h * Kk + k];

        float4 acc = make_float4(w4[Kk-1] * xv.x, w4[Kk-1] * xv.y,
                                 w4[Kk-1] * xv.z, w4[Kk-1] * xv.w);
        #pragma unroll
        for (int k = 0; k < Kk - 1; k++) {
            acc.x += w4[k] * win[k].x; acc.y += w4[k] * win[k].y;
            acc.z += w4[k] * win[k].z; acc.w += w4[k] * win[k].w;
        }

        float4 r = warp_ln(acc, lng, lnb, lane);
        stbf4(XLN2 + p * Cc + lane * 4, r);
        uint32_t u = (uint32_t)f2e4m3x2(r.x, r.y)
                   | ((uint32_t)f2e4m3x2(r.z, r.w) << 16);
        *(uint32_t*)(XLN8 + p * Cc + lane * 4) = u;

        #pragma unroll
        for (int k = 0; k < Kk - 2; k++) win[k] = win[k + 1];
        win[Kk - 2] = xv;
    }
}

// ---------------------------------------------------------------------------
__global__ void wt_all_kernel(const float* __restrict__ fc1w,
                              const float* __restrict__ fc2w)
{
    __shared__ float tile[32][33];
    const int z = blockIdx.z;
    const int l = z >> 1;
    const bool is2 = (z & 1) != 0;
    const float* in = is2 ? fc2w + (size_t)l * Ff * Cc : fc1w + (size_t)l * Cc * Ff;
    uint8_t* out    = is2 ? g_WT2 + (size_t)l * Cc * Ff : g_WT1 + (size_t)l * Ff * Cc;
    const int Kd = is2 ? Ff : Cc;
    const int Nn = is2 ? Cc : Ff;
    const int nbx = Nn / 32;
    const int bx = blockIdx.x % nbx, by = blockIdx.x / nbx;

    int x = bx * 32 + threadIdx.x;
    int y = by * 32 + threadIdx.y;
    #pragma unroll
    for (int j = 0; j < 4; j++)
        tile[threadIdx.y + j * 8][threadIdx.x] = in[(size_t)(y + j * 8) * Nn + x];
    __syncthreads();
    int n = bx * 32 + threadIdx.y;
    int k = by * 32 + threadIdx.x;
    #pragma unroll
    for (int j = 0; j < 4; j++)
        out[(size_t)(n + j * 8) * Kd + k] =
            (uint8_t)(f2e4m3x2(tile[threadIdx.x][threadIdx.y + j * 8], 0.f) & 0xFF);
}

// ---------------------------------------------------------------------------
// Fused MLP (occ 2): CTA = 128 tokens, 256 threads, 112KB smem.
// Phase-2 re-tiled 4x2 (B-fragment replication 8x -> 4x); LN via smem partials.
// ---------------------------------------------------------------------------
#define MLP_SMEM 114688
#define SHOFF 0u
#define SAOFF 65536u
#define SBOFF 81920u

__device__ __forceinline__ void load_b1_tile(uint32_t sbuf, const uint8_t* W1,
                                             int nt, int tid)
{
    int row = tid >> 1, j0 = (tid & 1) * 4;
    const uint8_t* src = W1 + (size_t)(nt * 128 + row) * 128;
    #pragma unroll
    for (int jj = 0; jj < 4; jj++) {
        int j = j0 + jj;
        uint32_t d = sbuf + row * 128 + (((j >> 2) ^ (row & 1)) << 6)
                   + (((j & 3) ^ ((row >> 1) & 3)) << 4);
        cp16(d, src + j * 16);
    }
}
__device__ __forceinline__ void load_b2_chunk(uint32_t sring, const uint8_t* W2,
                                              int kc, int tid)
{
    int row = tid >> 1;
    #pragma unroll
    for (int cc = 0; cc < 2; cc++) {
        int c = (tid & 1) * 2 + cc;
        uint32_t d = sring + row * 64 + ((c ^ ((row >> 1) & 3)) << 4);
        cp16(d, W2 + (size_t)row * 512 + kc * 64 + c * 16);
    }
}
__device__ __forceinline__ uint32_t hoff(int row, int col)
{
    return (uint32_t)(row * 512 + (((col >> 6) ^ (row & 7)) << 6)
         + ((((col >> 4) & 3) ^ ((row >> 1) & 3)) << 4) + (col & 15));
}

__global__ void __launch_bounds__(256, 2)
mlp_fused(const uint8_t* __restrict__ A8,
          const uint8_t* __restrict__ W1,
          const uint8_t* __restrict__ W2,
          const float* __restrict__ b1,
          const float* __restrict__ b2,
          const __nv_bfloat16* __restrict__ res,
          __nv_bfloat16* __restrict__ out,
          const float* __restrict__ sg,
          const float* __restrict__ sb)
{
    extern __shared__ __align__(1024) char sm[];
    const uint32_t S = smem_to_u32(sm);
    const uint32_t SH = S + SHOFF, SA = S + SAOFF, SB = S + SBOFF;
    const int tid = threadIdx.x, wid = tid >> 5, lane = tid & 31;
    const int bm = blockIdx.x * 128;
    const int lgrp = lane >> 3, l7 = lane & 7, g = lane >> 2, i4 = lane & 3;
    const int cA = lgrp >> 1, cB = lgrp & 1;

    const int lA = l7 + ((lgrp & 1) << 3);
    const int lB = l7 + ((lgrp >> 1) << 3);
    const int aX1 = lA & 1, aX2 = (lA >> 1) & 3, aX7 = lA & 7;
    const int bX1 = lB & 1, bX2 = (lB >> 1) & 3;
    const uint32_t aS[2] = { (uint32_t)((cA ^ aX2) << 4),
                             (uint32_t)(((2 | cA) ^ aX2) << 4) };
    const uint32_t bS[2] = { (uint32_t)((cB ^ bX2) << 4),
                             (uint32_t)(((2 | cB) ^ bX2) << 4) };

    // prologue: A tile + B1[0]
    {
        int row = tid >> 1, kb = tid & 1;
        const uint8_t* src = A8 + (size_t)(bm + row) * 128 + kb * 64;
        #pragma unroll
        for (int c = 0; c < 4; c++) {
            uint32_t d = SA + row * 128 + ((kb ^ (row & 1)) << 6)
                       + ((c ^ ((row >> 1) & 3)) << 4);
            cp16(d, src + c * 16);
        }
    }
    load_b1_tile(SB, W1, 0, tid);
    CP_COMMIT();

    const int wm = wid & 3, wn = wid >> 2;
    const uint32_t aRow = SA + wm * 4096 + lA * 128;
    const uint32_t bRowOff = wn * 8192 + lB * 128;

    #pragma unroll
    for (int nt = 0; nt < 4; nt++) {
        CP_WAIT0();
        __syncthreads();
        if (nt < 3) {
            load_b1_tile(SB + ((nt + 1) & 1) * 16384, W1, nt + 1, tid);
            CP_COMMIT();
        } else {
            load_b2_chunk(SB, W2, 0, tid);          CP_COMMIT();
            load_b2_chunk(SB + 8192, W2, 1, tid);   CP_COMMIT();
        }
        const uint32_t bRow = SB + (nt & 1) * 16384 + bRowOff;

        float acc[2][8][4] = {};
        #pragma unroll
        for (int kblk = 0; kblk < 2; kblk++) {
            const uint32_t aK = aRow + ((kblk ^ aX1) << 6);
            const uint32_t bK = bRow + ((kblk ^ bX1) << 6);
            #pragma unroll
            for (int s = 0; s < 2; s++) {
                uint32_t af[2][4], bf[4][4];
                #pragma unroll
                for (int mi = 0; mi < 2; mi++)
                    ldsm4(af[mi], aK + mi * 2048 + aS[s]);
                #pragma unroll
                for (int q = 0; q < 4; q++)
                    ldsm4(bf[q], bK + q * 2048 + bS[s]);
                #pragma unroll
                for (int mi = 0; mi < 2; mi++)
                    #pragma unroll
                    for (int ni = 0; ni < 8; ni++)
                        mma_fp8(acc[mi][ni], af[mi], &bf[ni >> 1][(ni & 1) * 2]);
            }
        }
        #pragma unroll
        for (int mi = 0; mi < 2; mi++) {
            int r = wm * 32 + mi * 16 + g;
            #pragma unroll
            for (int ni = 0; ni < 8; ni++) {
                int col = nt * 128 + wn * 64 + ni * 8 + i4 * 2;
                float bb0 = __ldg(b1 + col), bb1 = __ldg(b1 + col + 1);
                float v0 = fmaxf(acc[mi][ni][0] + bb0, 0.f);
                float v1 = fmaxf(acc[mi][ni][1] + bb1, 0.f);
                float v2 = fmaxf(acc[mi][ni][2] + bb0, 0.f);
                float v3 = fmaxf(acc[mi][ni][3] + bb1, 0.f);
                *(uint16_t*)(sm + hoff(r, col))     = f2e4m3x2(v0, v1);
                *(uint16_t*)(sm + hoff(r + 8, col)) = f2e4m3x2(v2, v3);
            }
        }
    }

    __syncthreads();
    load_b2_chunk(SB + 16384, W2, 2, tid);
    CP_COMMIT();

    // ---- phase 2, 4x2 warp tiling: warp = 32 rows x 64 cols, K=512
    const uint32_t aP0 = SH + (wm * 32 + lA) * 512;        // + mi*8192
    const uint32_t bP  = (wn * 64 + lB) * 64;              // + q*1024 (+ring)

    float acc2[2][8][4] = {};
    #pragma unroll 2
    for (int kc = 0; kc < 8; kc++) {
        CP_WAIT2();
        __syncthreads();
        if (kc < 5) load_b2_chunk(SB + ((kc + 3) & 3) * 8192, W2, kc + 3, tid);
        CP_COMMIT();
        const uint32_t ring = SB + (kc & 3) * 8192 + bP;
        const uint32_t aK = aP0 + ((kc ^ aX7) << 6);

        #pragma unroll
        for (int s = 0; s < 2; s++) {
            uint32_t af[2][4], bf[4][4];
            #pragma unroll
            for (int mi = 0; mi < 2; mi++)
                ldsm4(af[mi], aK + mi * 8192 + aS[s]);
            #pragma unroll
            for (int q = 0; q < 4; q++)
                ldsm4(bf[q], ring + q * 1024 + bS[s]);
            #pragma unroll
            for (int mi = 0; mi < 2; mi++)
                #pragma unroll
                for (int ni = 0; ni < 8; ni++)
                    mma_fp8(acc2[mi][ni], af[mi], &bf[ni >> 1][(ni & 1) * 2]);
        }
    }

    // ---- epilogue: bias + residual, then shared-LN with cross-warp partials
    float* sums = (float*)(sm + SAOFF);        // [128][2] mean partials
    float* vsum = sums + 256;                  // [128][2] var partials

    #pragma unroll
    for (int mi = 0; mi < 2; mi++) {
        int r0 = bm + wm * 32 + mi * 16 + g;
        #pragma unroll
        for (int ni = 0; ni < 8; ni++) {
            int c = wn * 64 + ni * 8 + i4 * 2;
            float bb0 = __ldg(b2 + c), bb1 = __ldg(b2 + c + 1);
            uint32_t u0 = *(const uint32_t*)(res + (size_t)r0 * Cc + c);
            uint32_t u1 = *(const uint32_t*)(res + (size_t)(r0 + 8) * Cc + c);
            __nv_bfloat162 h0 = *reinterpret_cast<__nv_bfloat162*>(&u0);
            __nv_bfloat162 h1 = *reinterpret_cast<__nv_bfloat162*>(&u1);
            acc2[mi][ni][0] += bb0 + __low2float(h0);
            acc2[mi][ni][1] += bb1 + __high2float(h0);
            acc2[mi][ni][2] += bb0 + __low2float(h1);
            acc2[mi][ni][3] += bb1 + __high2float(h1);
        }
    }

    // mean partials (per half-row of 64 cols)
    float pp[4];
    #pragma unroll
    for (int mi = 0; mi < 2; mi++) {
        float a0 = 0.f, a1 = 0.f;
        #pragma unroll
        for (int ni = 0; ni < 8; ni++) {
            a0 += acc2[mi][ni][0] + acc2[mi][ni][1];
            a1 += acc2[mi][ni][2] + acc2[mi][ni][3];
        }
        pp[mi * 2] = a0; pp[mi * 2 + 1] = a1;
    }
    #pragma unroll
    for (int j = 0; j < 4; j++) {
        pp[j] += __shfl_xor_sync(0xffffffffu, pp[j], 1);
        pp[j] += __shfl_xor_sync(0xffffffffu, pp[j], 2);
    }
    __syncthreads();    // SA region free (phase-1 done); order before writes
    if (i4 == 0) {
        #pragma unroll
        for (int j = 0; j < 4; j++) {
            int rl = wm * 32 + (j >> 1) * 16 + (j & 1) * 8 + g;
            sums[rl * 2 + wn] = pp[j];
        }
    }
    __syncthreads();
    float mean[4];
    #pragma unroll
    for (int j = 0; j < 4; j++) {
        int rl = wm * 32 + (j >> 1) * 16 + (j & 1) * 8 + g;
        mean[j] = (sums[rl * 2] + sums[rl * 2 + 1]) * (1.0f / Cc);
    }
    // variance partials
    float qq[4];
    #pragma unroll
    for (int mi = 0; mi < 2; mi++) {
        float q0 = 0.f, q1 = 0.f;
        #pragma unroll
        for (int ni = 0; ni < 8; ni++) {
            float d0 = acc2[mi][ni][0] - mean[mi * 2];
            float d1 = acc2[mi][ni][1] - mean[mi * 2];
            float d2 = acc2[mi][ni][2] - mean[mi * 2 + 1];
            float d3 = acc2[mi][ni][3] - mean[mi * 2 + 1];
            q0 += d0 * d0 + d1 * d1;
            q1 += d2 * d2 + d3 * d3;
        }
        qq[mi * 2] = q0; qq[mi * 2 + 1] = q1;
    }
    #pragma unroll
    for (int j = 0; j < 4; j++) {
        qq[j] += __shfl_xor_sync(0xffffffffu, qq[j], 1);
        qq[j] += __shfl_xor_sync(0xffffffffu, qq[j], 2);
    }
    if (i4 == 0) {
        #pragma unroll
        for (int j = 0; j < 4; j++) {
            int rl = wm * 32 + (j >> 1) * 16 + (j & 1) * 8 + g;
            vsum[rl * 2 + wn] = qq[j];
        }
    }
    __syncthreads();
    float rstd[4];
    #pragma unroll
    for (int j = 0; j < 4; j++) {
        int rl = wm * 32 + (j >> 1) * 16 + (j & 1) * 8 + g;
        rstd[j] = rsqrtf((vsum[rl * 2] + vsum[rl * 2 + 1]) * (1.0f / Cc) + 1e-5f);
    }

    #pragma unroll
    for (int mi = 0; mi < 2; mi++) {
        int r0 = bm + wm * 32 + mi * 16 + g;
        float m0 = mean[mi * 2],     rs0 = rstd[mi * 2];
        float m1 = mean[mi * 2 + 1], rs1 = rstd[mi * 2 + 1];
        #pragma unroll
        for (int ni = 0; ni < 8; ni++) {
            int c = wn * 64 + ni * 8 + i4 * 2;
            float gg0 = __ldg(sg + c), gg1 = __ldg(sg + c + 1);
            float be0 = __ldg(sb + c), be1 = __ldg(sb + c + 1);
            __nv_bfloat162 o0 = __floats2bfloat162_rn(
                (acc2[mi][ni][0] - m0) * rs0 * gg0 + be0,
                (acc2[mi][ni][1] - m0) * rs0 * gg1 + be1);
            __nv_bfloat162 o1 = __floats2bfloat162_rn(
                (acc2[mi][ni][2] - m1) * rs1 * gg0 + be0,
                (acc2[mi][ni][3] - m1) * rs1 * gg1 + be1);
            *(uint32_t*)(out + (size_t)r0 * Cc + c)       = *(uint32_t*)&o0;
            *(uint32_t*)(out + (size_t)(r0 + 8) * Cc + c) = *(uint32_t*)&o1;
        }
    }
}

// ---------------------------------------------------------------------------
__global__ void loss_kernel(const __nv_bfloat16* __restrict__ se,
                            const float* __restrict__ emb,
                            const int* __restrict__ pos,
                            const int* __restrict__ neg,
                            float* __restrict__ pL, float* __restrict__ pM)
{
    int warp = threadIdx.x >> 5, lane = threadIdx.x & 31;
    int i = blockIdx.x * 8 + warp;
    int b = i / Tt, t = i - b * Tt;
    int p = t * Bb + b;

    float4 e  = ldbf4(se + (size_t)p * Cc + lane * 4);
    int pid = pos[i];
    int nid = neg[i];
    float4 pv = ((const float4*)(emb + (size_t)pid * Cc))[lane];
    float4 nv = ((const float4*)(emb + (size_t)nid * Cc))[lane];
    float dp = e.x*pv.x + e.y*pv.y + e.z*pv.z + e.w*pv.w;
    float dn = e.x*nv.x + e.y*nv.y + e.z*nv.z + e.w*nv.w;
    #pragma unroll
    for (int o = 16; o; o >>= 1) {
        dp += __shfl_xor_sync(0xffffffffu, dp, o);
        dn += __shfl_xor_sync(0xffffffffu, dn, o);
    }

    __shared__ float sL[8], sM[8];
    if (lane == 0) {
        float sp = 1.0f / (1.0f + expf(-dp));
        float sn = 1.0f / (1.0f + expf(-dn));
        float val = -logf(sp + 1e-24f) - logf(1.0f - sn + 1e-24f);
        float m = (pid != 0) ? 1.0f : 0.0f;
        sL[warp] = val * m;
        sM[warp] = m;
    }
    __syncthreads();
    if (threadIdx.x == 0) {
        float a = 0.f, mm = 0.f;
        #pragma unroll
        for (int w = 0; w < 8; w++) { a += sL[w]; mm += sM[w]; }
        pL[blockIdx.x] = a;
        pM[blockIdx.x] = mm;
    }
}

__global__ void reduce_kernel(const float* __restrict__ pL,
                              const float* __restrict__ pM,
                              float* __restrict__ out)
{
    __shared__ double sL[1024], sM[1024];
    double a = 0.0, m = 0.0;
    for (int i = threadIdx.x; i < NPART; i += 1024) { a += pL[i]; m += pM[i]; }
    sL[threadIdx.x] = a; sM[threadIdx.x] = m;
    __syncthreads();
    for (int s = 512; s; s >>= 1) {
        if (threadIdx.x < s) {
            sL[threadIdx.x] += sL[threadIdx.x + s];
            sM[threadIdx.x] += sM[threadIdx.x + s];
        }
        __syncthreads();
    }
    if (threadIdx.x == 0) out[0] = (float)(sL[0] / sM[0]);
}

// ---------------------------------------------------------------------------
extern "C" void kernel_launch(void* const* d_in, const int* in_sizes, int n_in,
                              void* d_out, int out_size)
{
    const float* item_emb = (const float*)d_in[0];
    const float* conv_w   = (const float*)d_in[1];
    const float* conv_b   = (const float*)d_in[2];
    const float* ln_g     = (const float*)d_in[3];
    const float* ln_b     = (const float*)d_in[4];
    const float* fc1_w    = (const float*)d_in[5];
    const float* fc1_b    = (const float*)d_in[6];
    const float* fc2_w    = (const float*)d_in[7];
    const float* fc2_b    = (const float*)d_in[8];
    const float* sln_g    = (const float*)d_in[9];
    const float* sln_b    = (const float*)d_in[10];
    const int*   seq      = (const int*)d_in[11];
    const int*   pos      = (const int*)d_in[12];
    const int*   neg      = (const int*)d_in[13];

    __nv_bfloat16 *XLN, *XLN2;
    float *pL, *pM;
    uint8_t *XLN8, *WT1, *WT2;
    cudaGetSymbolAddress((void**)&XLN,  g_XLN);
    cudaGetSymbolAddress((void**)&XLN2, g_XLN2);
    cudaGetSymbolAddress((void**)&XLN8, g_XLN8);
    cudaGetSymbolAddress((void**)&WT1,  g_WT1);
    cudaGetSymbolAddress((void**)&WT2,  g_WT2);
    cudaGetSymbolAddress((void**)&pL,   g_pL);
    cudaGetSymbolAddress((void**)&pM,   g_pM);

    cudaFuncSetAttribute(mlp_fused,
        cudaFuncAttributeMaxDynamicSharedMemorySize, MLP_SMEM);

    const int gr8 = BTt / 8;
    dim3 blk(256);

    wt_all_kernel<<<dim3(64, 1, Ll * 2), dim3(32, 8)>>>(fc1_w, fc2_w);

    embed_ln_kernel<<<gr8, blk>>>(item_emb, seq, sln_g, sln_b, XLN);

    for (int l = 0; l < Ll; l++) {
        conv_ln_kernel<<<dim3(Tt / 8, Bb / 8), blk>>>(
            XLN, conv_w + (size_t)l * Cc * HK, conv_b + (size_t)l * HK,
            ln_g + (size_t)l * Cc, ln_b + (size_t)l * Cc, XLN2, XLN8);
        mlp_fused<<<BTt / 128, 256, MLP_SMEM>>>(
            XLN8, WT1 + (size_t)l * Ff * Cc, WT2 + (size_t)l * Cc * Ff,
            fc1_b + (size_t)l * Ff, fc2_b + (size_t)l * Cc,
            XLN2, XLN, sln_g, sln_b);
    }

    loss_kernel<<<gr8, blk>>>(XLN, item_emb, pos, neg, pL, pM);
    reduce_kernel<<<1, 1024>>>(pL, pM, (float*)d_out);
}

// round 15
// speedup vs baseline: 1.0174x; 1.0174x over previous
#include <cuda_runtime.h>
#include <cuda_bf16.h>
#include <math.h>
#include <stdint.h>

// Problem constants
#define Tt 200
#define Bb 512
#define Cc 128
#define Hh 4
#define Kk 5
#define Ff 512
#define Ll 2
#define BTt (Tt*Bb)        // 102400 tokens
#define HK  (Hh*Kk)        // 20
#define NPART (BTt/8)

// Scratch (activations stored bf16; all math fp32)
__device__ __nv_bfloat16 g_XLN [BTt*Cc];
__device__ __nv_bfloat16 g_XLN2[BTt*Cc];
__device__ uint8_t g_XLN8[BTt*Cc];
__device__ uint8_t g_WT1 [Ll*Ff*Cc];
__device__ uint8_t g_WT2 [Ll*Cc*Ff];
__device__ float g_pL [NPART];
__device__ float g_pM [NPART];

// ---------------------------------------------------------------------------
__device__ __forceinline__ uint32_t smem_to_u32(const void* p) {
    uint32_t a;
    asm("{ .reg .u64 t; cvta.to.shared.u64 t, %1; cvt.u32.u64 %0, t; }" : "=r"(a) : "l"(p));
    return a;
}
__device__ __forceinline__ uint16_t f2e4m3x2(float lo, float hi) {
    uint16_t r;
    asm("cvt.rn.satfinite.e4m3x2.f32 %0, %1, %2;" : "=h"(r) : "f"(hi), "f"(lo));
    return r;
}
__device__ __forceinline__ void mma_fp8(float* c, const uint32_t* a, const uint32_t* b) {
    asm volatile(
        "mma.sync.aligned.m16n8k32.row.col.f32.e4m3.e4m3.f32 "
        "{%0,%1,%2,%3}, {%4,%5,%6,%7}, {%8,%9}, {%0,%1,%2,%3};\n"
        : "+f"(c[0]), "+f"(c[1]), "+f"(c[2]), "+f"(c[3])
        : "r"(a[0]), "r"(a[1]), "r"(a[2]), "r"(a[3]), "r"(b[0]), "r"(b[1]));
}
__device__ __forceinline__ void ldsm4(uint32_t* r, uint32_t addr) {
    asm volatile("ldmatrix.sync.aligned.m8n8.x4.shared.b16 {%0,%1,%2,%3}, [%4];"
        : "=r"(r[0]), "=r"(r[1]), "=r"(r[2]), "=r"(r[3]) : "r"(addr));
}
__device__ __forceinline__ void cp16(uint32_t dst, const void* src) {
    asm volatile("cp.async.cg.shared.global [%0], [%1], 16;" :: "r"(dst), "l"(src));
}
#define CP_COMMIT() asm volatile("cp.async.commit_group;" ::: "memory")
#define CP_WAIT0()  asm volatile("cp.async.wait_group 0;" ::: "memory")
#define CP_WAIT2()  asm volatile("cp.async.wait_group 2;" ::: "memory")

// bf16x4 <-> float4 helpers
__device__ __forceinline__ float4 ldbf4(const __nv_bfloat16* p) {
    uint2 u = *(const uint2*)p;
    __nv_bfloat162 a = *reinterpret_cast<__nv_bfloat162*>(&u.x);
    __nv_bfloat162 b = *reinterpret_cast<__nv_bfloat162*>(&u.y);
    return make_float4(__low2float(a), __high2float(a),
                       __low2float(b), __high2float(b));
}
__device__ __forceinline__ void stbf4(__nv_bfloat16* p, float4 v) {
    __nv_bfloat162 a = __floats2bfloat162_rn(v.x, v.y);
    __nv_bfloat162 b = __floats2bfloat162_rn(v.z, v.w);
    uint2 u;
    u.x = *(uint32_t*)&a; u.y = *(uint32_t*)&b;
    *(uint2*)p = u;
}

// warp-row LayerNorm (32-lane row of float4)
__device__ __forceinline__ float4 warp_ln(float4 v, const float* __restrict__ g,
                                          const float* __restrict__ beta, int lane)
{
    float s = v.x + v.y + v.z + v.w;
    #pragma unroll
    for (int o = 16; o; o >>= 1) s += __shfl_xor_sync(0xffffffffu, s, o);
    float mean = s * (1.0f / Cc);
    float dx = v.x - mean, dy = v.y - mean, dz = v.z - mean, dw = v.w - mean;
    float q = dx*dx + dy*dy + dz*dz + dw*dw;
    #pragma unroll
    for (int o = 16; o; o >>= 1) q += __shfl_xor_sync(0xffffffffu, q, o);
    float rstd = rsqrtf(q * (1.0f / Cc) + 1e-5f);
    float4 gv = ((const float4*)g)[lane];
    float4 bv = ((const float4*)beta)[lane];
    float4 r;
    r.x = dx * rstd * gv.x + bv.x;
    r.y = dy * rstd * gv.y + bv.y;
    r.z = dz * rstd * gv.z + bv.z;
    r.w = dw * rstd * gv.w + bv.w;
    return r;
}

// ---------------------------------------------------------------------------
// Dynamic conv + per-layer LN, sliding window.
// EMB=true (layer 0): input rows are LN(item_emb[seq]) gathered on the fly.
// EMB=false: input rows read from XLN (bf16).
// Warp owns batch b, 8 consecutive timesteps; K=5 window rotates in registers.
// ---------------------------------------------------------------------------
template<bool EMB>
__global__ void conv_ln_kernel(const __nv_bfloat16* __restrict__ XLN,
                               const float* __restrict__ emb,
                               const int* __restrict__ seq,
                               const float* __restrict__ sg,
                               const float* __restrict__ sb,
                               const float* __restrict__ cw,
                               const float* __restrict__ cb,
                               const float* __restrict__ lng,
                               const float* __restrict__ lnb,
                               __nv_bfloat16* __restrict__ XLN2,
                               uint8_t* __restrict__ XLN8)
{
    __shared__ float  ws[Cc * HK];
    __shared__ float4 xs[8][32];
    __shared__ float  lg[8][HK];
    __shared__ float  wt[8][HK];

    const int tid = threadIdx.x, warp = tid >> 5, lane = tid & 31;
    const int t0 = blockIdx.x * 8;
    const int b  = blockIdx.y * 8 + warp;
    const int h  = lane >> 3;

    #pragma unroll
    for (int i = 0; i < (Cc * HK) / 256; i++)
        ws[i * 256 + tid] = cw[i * 256 + tid];
    __syncthreads();

    // row loader: XLN row (bf16) or LN(emb[seq]) for layer 0
    auto load_row = [&](int t) -> float4 {
        if (EMB) {
            int id = seq[b * Tt + t];
            float4 v = ((const float4*)(emb + (size_t)id * Cc))[lane];
            return warp_ln(v, sg, sb, lane);
        } else {
            return ldbf4(XLN + ((size_t)t * Bb + b) * Cc + lane * 4);
        }
    };

    float4 win[Kk - 1];
    #pragma unroll
    for (int k = 0; k < Kk - 1; k++) {
        int ts = t0 - (Kk - 1) + k;
        win[k] = (ts >= 0) ? load_row(ts) : make_float4(0.f, 0.f, 0.f, 0.f);
    }

    for (int it = 0; it < 8; it++) {
        const int t = t0 + it;
        const size_t p = (size_t)t * Bb + b;
        float4 xv = load_row(t);
        xs[warp][lane] = xv;
        __syncwarp();

        float e = 0.0f;
        if (lane < HK) {
            float acc = __ldg(cb + lane);
            #pragma unroll 8
            for (int c4 = 0; c4 < 32; c4++) {
                float4 xq = xs[warp][c4];
                const float* wr = &ws[c4 * 4 * HK + lane];
                acc += xq.x * wr[0] + xq.y * wr[HK]
                     + xq.z * wr[2 * HK] + xq.w * wr[3 * HK];
            }
            lg[warp][lane] = acc;
        }
        __syncwarp();
        if (lane < HK) {
            int hb = (lane / Kk) * Kk;
            float m = lg[warp][hb];
            #pragma unroll
            for (int k = 1; k < Kk; k++) m = fmaxf(m, lg[warp][hb + k]);
            e = expf(lg[warp][lane] - m);
            wt[warp][lane] = e;
        }
        __syncwarp();
        float sden = 0.0f;
        if (lane < HK) {
            int hb = (lane / Kk) * Kk;
            #pragma unroll
            for (int k = 0; k < Kk; k++) sden += wt[warp][hb + k];
        }
        __syncwarp();
        if (lane < HK) wt[warp][lane] = e / sden;
        __syncwarp();

        float w4[Kk];
        #pragma unroll
        for (int k = 0; k < Kk; k++) w4[k] = wt[warp][h * Kk + k];

        float4 acc = make_float4(w4[Kk-1] * xv.x, w4[Kk-1] * xv.y,
                                 w4[Kk-1] * xv.z, w4[Kk-1] * xv.w);
        #pragma unroll
        for (int k = 0; k < Kk - 1; k++) {
            acc.x += w4[k] * win[k].x; acc.y += w4[k] * win[k].y;
            acc.z += w4[k] * win[k].z; acc.w += w4[k] * win[k].w;
        }

        float4 r = warp_ln(acc, lng, lnb, lane);
        stbf4(XLN2 + p * Cc + lane * 4, r);
        uint32_t u = (uint32_t)f2e4m3x2(r.x, r.y)
                   | ((uint32_t)f2e4m3x2(r.z, r.w) << 16);
        *(uint32_t*)(XLN8 + p * Cc + lane * 4) = u;

        #pragma unroll
        for (int k = 0; k < Kk - 2; k++) win[k] = win[k + 1];
        win[Kk - 2] = xv;
    }
}

// ---------------------------------------------------------------------------
__global__ void wt_all_kernel(const float* __restrict__ fc1w,
                              const float* __restrict__ fc2w)
{
    __shared__ float tile[32][33];
    const int z = blockIdx.z;
    const int l = z >> 1;
    const bool is2 = (z & 1) != 0;
    const float* in = is2 ? fc2w + (size_t)l * Ff * Cc : fc1w + (size_t)l * Cc * Ff;
    uint8_t* out    = is2 ? g_WT2 + (size_t)l * Cc * Ff : g_WT1 + (size_t)l * Ff * Cc;
    const int Kd = is2 ? Ff : Cc;
    const int Nn = is2 ? Cc : Ff;
    const int nbx = Nn / 32;
    const int bx = blockIdx.x % nbx, by = blockIdx.x / nbx;

    int x = bx * 32 + threadIdx.x;
    int y = by * 32 + threadIdx.y;
    #pragma unroll
    for (int j = 0; j < 4; j++)
        tile[threadIdx.y + j * 8][threadIdx.x] = in[(size_t)(y + j * 8) * Nn + x];
    __syncthreads();
    int n = bx * 32 + threadIdx.y;
    int k = by * 32 + threadIdx.x;
    #pragma unroll
    for (int j = 0; j < 4; j++)
        out[(size_t)(n + j * 8) * Kd + k] =
            (uint8_t)(f2e4m3x2(tile[threadIdx.x][threadIdx.y + j * 8], 0.f) & 0xFF);
}

// ---------------------------------------------------------------------------
// Fused MLP (occ 2): CTA = 128 tokens, 256 threads, 112KB smem. (R12 version,
// converged: phase-2 8-warp full-row, register shared-LN.)
// ---------------------------------------------------------------------------
#define MLP_SMEM 114688
#define SHOFF 0u
#define SAOFF 65536u
#define SBOFF 81920u

__device__ __forceinline__ void load_b1_tile(uint32_t sbuf, const uint8_t* W1,
                                             int nt, int tid)
{
    int row = tid >> 1, j0 = (tid & 1) * 4;
    const uint8_t* src = W1 + (size_t)(nt * 128 + row) * 128;
    #pragma unroll
    for (int jj = 0; jj < 4; jj++) {
        int j = j0 + jj;
        uint32_t d = sbuf + row * 128 + (((j >> 2) ^ (row & 1)) << 6)
                   + (((j & 3) ^ ((row >> 1) & 3)) << 4);
        cp16(d, src + j * 16);
    }
}
__device__ __forceinline__ void load_b2_chunk(uint32_t sring, const uint8_t* W2,
                                              int kc, int tid)
{
    int row = tid >> 1;
    #pragma unroll
    for (int cc = 0; cc < 2; cc++) {
        int c = (tid & 1) * 2 + cc;
        uint32_t d = sring + row * 64 + ((c ^ ((row >> 1) & 3)) << 4);
        cp16(d, W2 + (size_t)row * 512 + kc * 64 + c * 16);
    }
}
__device__ __forceinline__ uint32_t hoff(int row, int col)
{
    return (uint32_t)(row * 512 + (((col >> 6) ^ (row & 7)) << 6)
         + ((((col >> 4) & 3) ^ ((row >> 1) & 3)) << 4) + (col & 15));
}

__global__ void __launch_bounds__(256, 2)
mlp_fused(const uint8_t* __restrict__ A8,
          const uint8_t* __restrict__ W1,
          const uint8_t* __restrict__ W2,
          const float* __restrict__ b1,
          const float* __restrict__ b2,
          const __nv_bfloat16* __restrict__ res,
          __nv_bfloat16* __restrict__ out,
          const float* __restrict__ sg,
          const float* __restrict__ sb)
{
    extern __shared__ __align__(1024) char sm[];
    const uint32_t S = smem_to_u32(sm);
    const uint32_t SH = S + SHOFF, SA = S + SAOFF, SB = S + SBOFF;
    const int tid = threadIdx.x, wid = tid >> 5, lane = tid & 31;
    const int bm = blockIdx.x * 128;
    const int lgrp = lane >> 3, l7 = lane & 7, g = lane >> 2, i4 = lane & 3;
    const int cA = lgrp >> 1, cB = lgrp & 1;

    const int lA = l7 + ((lgrp & 1) << 3);
    const int lB = l7 + ((lgrp >> 1) << 3);
    const int aX1 = lA & 1, aX2 = (lA >> 1) & 3, aX7 = lA & 7;
    const int bX1 = lB & 1, bX2 = (lB >> 1) & 3;
    const uint32_t aS[2] = { (uint32_t)((cA ^ aX2) << 4),
                             (uint32_t)(((2 | cA) ^ aX2) << 4) };
    const uint32_t bS[2] = { (uint32_t)((cB ^ bX2) << 4),
                             (uint32_t)(((2 | cB) ^ bX2) << 4) };

    {
        int row = tid >> 1, kb = tid & 1;
        const uint8_t* src = A8 + (size_t)(bm + row) * 128 + kb * 64;
        #pragma unroll
        for (int c = 0; c < 4; c++) {
            uint32_t d = SA + row * 128 + ((kb ^ (row & 1)) << 6)
                       + ((c ^ ((row >> 1) & 3)) << 4);
            cp16(d, src + c * 16);
        }
    }
    load_b1_tile(SB, W1, 0, tid);
    CP_COMMIT();

    const int wm = wid & 3, wn = wid >> 2;
    const uint32_t aRow = SA + wm * 4096 + lA * 128;
    const uint32_t bRowOff = wn * 8192 + lB * 128;

    #pragma unroll
    for (int nt = 0; nt < 4; nt++) {
        CP_WAIT0();
        __syncthreads();
        if (nt < 3) {
            load_b1_tile(SB + ((nt + 1) & 1) * 16384, W1, nt + 1, tid);
            CP_COMMIT();
        } else {
            load_b2_chunk(SB, W2, 0, tid);          CP_COMMIT();
            load_b2_chunk(SB + 8192, W2, 1, tid);   CP_COMMIT();
        }
        const uint32_t bRow = SB + (nt & 1) * 16384 + bRowOff;

        float acc[2][8][4] = {};
        #pragma unroll
        for (int kblk = 0; kblk < 2; kblk++) {
            const uint32_t aK = aRow + ((kblk ^ aX1) << 6);
            const uint32_t bK = bRow + ((kblk ^ bX1) << 6);
            #pragma unroll
            for (int s = 0; s < 2; s++) {
                uint32_t af[2][4], bf[4][4];
                #pragma unroll
                for (int mi = 0; mi < 2; mi++)
                    ldsm4(af[mi], aK + mi * 2048 + aS[s]);
                #pragma unroll
                for (int q = 0; q < 4; q++)
                    ldsm4(bf[q], bK + q * 2048 + bS[s]);
                #pragma unroll
                for (int mi = 0; mi < 2; mi++)
                    #pragma unroll
                    for (int ni = 0; ni < 8; ni++)
                        mma_fp8(acc[mi][ni], af[mi], &bf[ni >> 1][(ni & 1) * 2]);
            }
        }
        #pragma unroll
        for (int mi = 0; mi < 2; mi++) {
            int r = wm * 32 + mi * 16 + g;
            #pragma unroll
            for (int ni = 0; ni < 8; ni++) {
                int col = nt * 128 + wn * 64 + ni * 8 + i4 * 2;
                float bb0 = __ldg(b1 + col), bb1 = __ldg(b1 + col + 1);
                float v0 = fmaxf(acc[mi][ni][0] + bb0, 0.f);
                float v1 = fmaxf(acc[mi][ni][1] + bb1, 0.f);
                float v2 = fmaxf(acc[mi][ni][2] + bb0, 0.f);
                float v3 = fmaxf(acc[mi][ni][3] + bb1, 0.f);
                *(uint16_t*)(sm + hoff(r, col))     = f2e4m3x2(v0, v1);
                *(uint16_t*)(sm + hoff(r + 8, col)) = f2e4m3x2(v2, v3);
            }
        }
    }

    __syncthreads();
    load_b2_chunk(SB + 16384, W2, 2, tid);
    CP_COMMIT();

    const uint32_t pRow = SH + (wid * 16 + lA) * 512;

    float acc2[16][4] = {};
    #pragma unroll 2
    for (int kc = 0; kc < 8; kc++) {
        CP_WAIT2();
        __syncthreads();
        if (kc < 5) load_b2_chunk(SB + ((kc + 3) & 3) * 8192, W2, kc + 3, tid);
        CP_COMMIT();
        const uint32_t ring = SB + (kc & 3) * 8192 + lB * 64;
        const uint32_t aK = pRow + ((kc ^ aX7) << 6);

        #pragma unroll
        for (int s = 0; s < 2; s++) {
            uint32_t af[4];
            ldsm4(af, aK + aS[s]);
            const uint32_t rb = ring + bS[s];
            #pragma unroll
            for (int half = 0; half < 2; half++) {
                uint32_t bf[4][4];
                #pragma unroll
                for (int q = 0; q < 4; q++)
                    ldsm4(bf[q], rb + (half * 4 + q) * 1024);
                #pragma unroll
                for (int ni = 0; ni < 8; ni++)
                    mma_fp8(acc2[half * 8 + ni], af, &bf[ni >> 1][(ni & 1) * 2]);
            }
        }
    }

    const int rg = wid * 16 + g;
    const __nv_bfloat16* r0p = res + (size_t)(bm + rg) * Cc;
    const __nv_bfloat16* r1p = res + (size_t)(bm + rg + 8) * Cc;
    #pragma unroll
    for (int ni = 0; ni < 16; ni++) {
        int c = ni * 8 + i4 * 2;
        float bb0 = __ldg(b2 + c), bb1 = __ldg(b2 + c + 1);
        uint32_t u0 = *(const uint32_t*)(r0p + c);
        uint32_t u1 = *(const uint32_t*)(r1p + c);
        __nv_bfloat162 h0 = *reinterpret_cast<__nv_bfloat162*>(&u0);
        __nv_bfloat162 h1 = *reinterpret_cast<__nv_bfloat162*>(&u1);
        acc2[ni][0] += bb0 + __low2float(h0);  acc2[ni][1] += bb1 + __high2float(h0);
        acc2[ni][2] += bb0 + __low2float(h1);  acc2[ni][3] += bb1 + __high2float(h1);
    }
    float s1 = 0.f, s2 = 0.f;
    #pragma unroll
    for (int ni = 0; ni < 16; ni++) {
        s1 += acc2[ni][0] + acc2[ni][1];
        s2 += acc2[ni][2] + acc2[ni][3];
    }
    s1 += __shfl_xor_sync(0xffffffffu, s1, 1); s1 += __shfl_xor_sync(0xffffffffu, s1, 2);
    s2 += __shfl_xor_sync(0xffffffffu, s2, 1); s2 += __shfl_xor_sync(0xffffffffu, s2, 2);
    float m1 = s1 * (1.0f / Cc), m2 = s2 * (1.0f / Cc);
    float q1 = 0.f, q2 = 0.f;
    #pragma unroll
    for (int ni = 0; ni < 16; ni++) {
        float d0 = acc2[ni][0] - m1, d1 = acc2[ni][1] - m1;
        float d2 = acc2[ni][2] - m2, d3 = acc2[ni][3] - m2;
        q1 += d0 * d0 + d1 * d1;
        q2 += d2 * d2 + d3 * d3;
    }
    q1 += __shfl_xor_sync(0xffffffffu, q1, 1); q1 += __shfl_xor_sync(0xffffffffu, q1, 2);
    q2 += __shfl_xor_sync(0xffffffffu, q2, 1); q2 += __shfl_xor_sync(0xffffffffu, q2, 2);
    float rs1 = rsqrtf(q1 * (1.0f / Cc) + 1e-5f);
    float rs2 = rsqrtf(q2 * (1.0f / Cc) + 1e-5f);
    __nv_bfloat16* o0p = out + (size_t)(bm + rg) * Cc;
    __nv_bfloat16* o1p = out + (size_t)(bm + rg + 8) * Cc;
    #pragma unroll
    for (int ni = 0; ni < 16; ni++) {
        int c = ni * 8 + i4 * 2;
        float gg0 = __ldg(sg + c), gg1 = __ldg(sg + c + 1);
        float be0 = __ldg(sb + c), be1 = __ldg(sb + c + 1);
        __nv_bfloat162 o0 = __floats2bfloat162_rn(
            (acc2[ni][0] - m1) * rs1 * gg0 + be0,
            (acc2[ni][1] - m1) * rs1 * gg1 + be1);
        __nv_bfloat162 o1 = __floats2bfloat162_rn(
            (acc2[ni][2] - m2) * rs2 * gg0 + be0,
            (acc2[ni][3] - m2) * rs2 * gg1 + be1);
        *(uint32_t*)(o0p + c) = *(uint32_t*)&o0;
        *(uint32_t*)(o1p + c) = *(uint32_t*)&o1;
    }
}

// ---------------------------------------------------------------------------
__global__ void loss_kernel(const __nv_bfloat16* __restrict__ se,
                            const float* __restrict__ emb,
                            const int* __restrict__ pos,
                            const int* __restrict__ neg,
                            float* __restrict__ pL, float* __restrict__ pM)
{
    int warp = threadIdx.x >> 5, lane = threadIdx.x & 31;
    int i = blockIdx.x * 8 + warp;
    int b = i / Tt, t = i - b * Tt;
    int p = t * Bb + b;

    float4 e  = ldbf4(se + (size_t)p * Cc + lane * 4);
    int pid = pos[i];
    int nid = neg[i];
    float4 pv = ((const float4*)(emb + (size_t)pid * Cc))[lane];
    float4 nv = ((const float4*)(emb + (size_t)nid * Cc))[lane];
    float dp = e.x*pv.x + e.y*pv.y + e.z*pv.z + e.w*pv.w;
    float dn = e.x*nv.x + e.y*nv.y + e.z*nv.z + e.w*nv.w;
    #pragma unroll
    for (int o = 16; o; o >>= 1) {
        dp += __shfl_xor_sync(0xffffffffu, dp, o);
        dn += __shfl_xor_sync(0xffffffffu, dn, o);
    }

    __shared__ float sL[8], sM[8];
    if (lane == 0) {
        float sp = 1.0f / (1.0f + expf(-dp));
        float sn = 1.0f / (1.0f + expf(-dn));
        float val = -logf(sp + 1e-24f) - logf(1.0f - sn + 1e-24f);
        float m = (pid != 0) ? 1.0f : 0.0f;
        sL[warp] = val * m;
        sM[warp] = m;
    }
    __syncthreads();
    if (threadIdx.x == 0) {
        float a = 0.f, mm = 0.f;
        #pragma unroll
        for (int w = 0; w < 8; w++) { a += sL[w]; mm += sM[w]; }
        pL[blockIdx.x] = a;
        pM[blockIdx.x] = mm;
    }
}

__global__ void reduce_kernel(const float* __restrict__ pL,
                              const float* __restrict__ pM,
                              float* __restrict__ out)
{
    __shared__ double sL[1024], sM[1024];
    double a = 0.0, m = 0.0;
    for (int i = threadIdx.x; i < NPART; i += 1024) { a += pL[i]; m += pM[i]; }
    sL[threadIdx.x] = a; sM[threadIdx.x] = m;
    __syncthreads();
    for (int s = 512; s; s >>= 1) {
        if (threadIdx.x < s) {
            sL[threadIdx.x] += sL[threadIdx.x + s];
            sM[threadIdx.x] += sM[threadIdx.x + s];
        }
        __syncthreads();
    }
    if (threadIdx.x == 0) out[0] = (float)(sL[0] / sM[0]);
}

// ---------------------------------------------------------------------------
extern "C" void kernel_launch(void* const* d_in, const int* in_sizes, int n_in,
                              void* d_out, int out_size)
{
    const float* item_emb = (const float*)d_in[0];
    const float* conv_w   = (const float*)d_in[1];
    const float* conv_b   = (const float*)d_in[2];
    const float* ln_g     = (const float*)d_in[3];
    const float* ln_b     = (const float*)d_in[4];
    const float* fc1_w    = (const float*)d_in[5];
    const float* fc1_b    = (const float*)d_in[6];
    const float* fc2_w    = (const float*)d_in[7];
    const float* fc2_b    = (const float*)d_in[8];
    const float* sln_g    = (const float*)d_in[9];
    const float* sln_b    = (const float*)d_in[10];
    const int*   seq      = (const int*)d_in[11];
    const int*   pos      = (const int*)d_in[12];
    const int*   neg      = (const int*)d_in[13];

    __nv_bfloat16 *XLN, *XLN2;
    float *pL, *pM;
    uint8_t *XLN8, *WT1, *WT2;
    cudaGetSymbolAddress((void**)&XLN,  g_XLN);
    cudaGetSymbolAddress((void**)&XLN2, g_XLN2);
    cudaGetSymbolAddress((void**)&XLN8, g_XLN8);
    cudaGetSymbolAddress((void**)&WT1,  g_WT1);
    cudaGetSymbolAddress((void**)&WT2,  g_WT2);
    cudaGetSymbolAddress((void**)&pL,   g_pL);
    cudaGetSymbolAddress((void**)&pM,   g_pM);

    cudaFuncSetAttribute(mlp_fused,
        cudaFuncAttributeMaxDynamicSharedMemorySize, MLP_SMEM);

    const int gr8 = BTt / 8;
    dim3 blk(256);
    dim3 cgrid(Tt / 8, Bb / 8);

    wt_all_kernel<<<dim3(64, 1, Ll * 2), dim3(32, 8)>>>(fc1_w, fc2_w);

    // layer 0: conv consumes LN(emb[seq]) directly (embed kernel fused away)
    conv_ln_kernel<true><<<cgrid, blk>>>(
        nullptr, item_emb, seq, sln_g, sln_b,
        conv_w, conv_b, ln_g, ln_b, XLN2, XLN8);
    mlp_fused<<<BTt / 128, 256, MLP_SMEM>>>(
        XLN8, WT1, WT2, fc1_b, fc2_b, XLN2, XLN, sln_g, sln_b);

    // layer 1
    conv_ln_kernel<false><<<cgrid, blk>>>(
        XLN, nullptr, nullptr, nullptr, nullptr,
        conv_w + (size_t)Cc * HK, conv_b + HK,
        ln_g + Cc, ln_b + Cc, XLN2, XLN8);
    mlp_fused<<<BTt / 128, 256, MLP_SMEM>>>(
        XLN8, WT1 + (size_t)Ff * Cc, WT2 + (size_t)Cc * Ff,
        fc1_b + Ff, fc2_b + Cc, XLN2, XLN, sln_g, sln_b);

    loss_kernel<<<gr8, blk>>>(XLN, item_emb, pos, neg, pL, pM);
    reduce_kernel<<<1, 1024>>>(pL, pM, (float*)d_out);
}

// round 16
// speedup vs baseline: 1.1986x; 1.1781x over previous
#include <cuda_runtime.h>
#include <cuda_bf16.h>
#include <math.h>
#include <stdint.h>

// Problem constants
#define Tt 200
#define Bb 512
#define Cc 128
#define Hh 4
#define Kk 5
#define Ff 512
#define Ll 2
#define BTt (Tt*Bb)        // 102400 tokens
#define HK  (Hh*Kk)        // 20
#define NPART (BTt/8)

// Scratch (activations stored bf16; all math fp32)
__device__ __nv_bfloat16 g_XLN [BTt*Cc];
__device__ __nv_bfloat16 g_XLN2[BTt*Cc];
__device__ uint8_t g_XLN8[BTt*Cc];
__device__ uint8_t g_WT1 [Ll*Ff*Cc];
__device__ uint8_t g_WT2 [Ll*Cc*Ff];
__device__ float g_pL [NPART];
__device__ float g_pM [NPART];

// ---------------------------------------------------------------------------
__device__ __forceinline__ uint32_t smem_to_u32(const void* p) {
    uint32_t a;
    asm("{ .reg .u64 t; cvta.to.shared.u64 t, %1; cvt.u32.u64 %0, t; }" : "=r"(a) : "l"(p));
    return a;
}
__device__ __forceinline__ uint16_t f2e4m3x2(float lo, float hi) {
    uint16_t r;
    asm("cvt.rn.satfinite.e4m3x2.f32 %0, %1, %2;" : "=h"(r) : "f"(hi), "f"(lo));
    return r;
}
__device__ __forceinline__ void mma_fp8(float* c, const uint32_t* a, const uint32_t* b) {
    asm volatile(
        "mma.sync.aligned.m16n8k32.row.col.f32.e4m3.e4m3.f32 "
        "{%0,%1,%2,%3}, {%4,%5,%6,%7}, {%8,%9}, {%0,%1,%2,%3};\n"
        : "+f"(c[0]), "+f"(c[1]), "+f"(c[2]), "+f"(c[3])
        : "r"(a[0]), "r"(a[1]), "r"(a[2]), "r"(a[3]), "r"(b[0]), "r"(b[1]));
}
__device__ __forceinline__ void ldsm4(uint32_t* r, uint32_t addr) {
    asm volatile("ldmatrix.sync.aligned.m8n8.x4.shared.b16 {%0,%1,%2,%3}, [%4];"
        : "=r"(r[0]), "=r"(r[1]), "=r"(r[2]), "=r"(r[3]) : "r"(addr));
}
__device__ __forceinline__ void cp16(uint32_t dst, const void* src) {
    asm volatile("cp.async.cg.shared.global [%0], [%1], 16;" :: "r"(dst), "l"(src));
}
#define CP_COMMIT() asm volatile("cp.async.commit_group;" ::: "memory")
#define CP_WAIT0()  asm volatile("cp.async.wait_group 0;" ::: "memory")
#define CP_WAIT2()  asm volatile("cp.async.wait_group 2;" ::: "memory")

// bf16x4 <-> float4 helpers
__device__ __forceinline__ float4 ldbf4(const __nv_bfloat16* p) {
    uint2 u = *(const uint2*)p;
    __nv_bfloat162 a = *reinterpret_cast<__nv_bfloat162*>(&u.x);
    __nv_bfloat162 b = *reinterpret_cast<__nv_bfloat162*>(&u.y);
    return make_float4(__low2float(a), __high2float(a),
                       __low2float(b), __high2float(b));
}
__device__ __forceinline__ void stbf4(__nv_bfloat16* p, float4 v) {
    __nv_bfloat162 a = __floats2bfloat162_rn(v.x, v.y);
    __nv_bfloat162 b = __floats2bfloat162_rn(v.z, v.w);
    uint2 u;
    u.x = *(uint32_t*)&a; u.y = *(uint32_t*)&b;
    *(uint2*)p = u;
}

// warp-row LayerNorm (32-lane row of float4)
__device__ __forceinline__ float4 warp_ln(float4 v, const float* __restrict__ g,
                                          const float* __restrict__ beta, int lane)
{
    float s = v.x + v.y + v.z + v.w;
    #pragma unroll
    for (int o = 16; o; o >>= 1) s += __shfl_xor_sync(0xffffffffu, s, o);
    float mean = s * (1.0f / Cc);
    float dx = v.x - mean, dy = v.y - mean, dz = v.z - mean, dw = v.w - mean;
    float q = dx*dx + dy*dy + dz*dz + dw*dw;
    #pragma unroll
    for (int o = 16; o; o >>= 1) q += __shfl_xor_sync(0xffffffffu, q, o);
    float rstd = rsqrtf(q * (1.0f / Cc) + 1e-5f);
    float4 gv = ((const float4*)g)[lane];
    float4 bv = ((const float4*)beta)[lane];
    float4 r;
    r.x = dx * rstd * gv.x + bv.x;
    r.y = dy * rstd * gv.y + bv.y;
    r.z = dz * rstd * gv.z + bv.z;
    r.w = dw * rstd * gv.w + bv.w;
    return r;
}

// ---------------------------------------------------------------------------
// Dynamic conv + per-layer LN; 8-token batched logit GEMV (ws reads amortized).
// Warp owns (b, t0..t0+7); 12 rows staged in dynamic smem.
// EMB=true: rows are LN(item_emb[seq]) gathered on the fly (layer 0).
// ---------------------------------------------------------------------------
#define CONV_SMEM (8 * 12 * 32 * 16)   // xs[8 warps][12 rows][32] float4 = 48KB

template<bool EMB>
__global__ void conv_ln_kernel(const __nv_bfloat16* __restrict__ XLN,
                               const float* __restrict__ emb,
                               const int* __restrict__ seq,
                               const float* __restrict__ sg,
                               const float* __restrict__ sb,
                               const float* __restrict__ cw,
                               const float* __restrict__ cb,
                               const float* __restrict__ lng,
                               const float* __restrict__ lnb,
                               __nv_bfloat16* __restrict__ XLN2,
                               uint8_t* __restrict__ XLN8)
{
    extern __shared__ float4 xs[];              // [8][12][32]
    __shared__ float ws[Cc * HK];
    __shared__ float lg[8][HK];
    __shared__ float ew[8][8][HK];              // exp values per (warp, tok, j)

    const int tid = threadIdx.x, warp = tid >> 5, lane = tid & 31;
    const int t0 = blockIdx.x * 8;
    const int b  = blockIdx.y * 8 + warp;
    const int h  = lane >> 3;

    #pragma unroll
    for (int i = 0; i < (Cc * HK) / 256; i++)
        ws[i * 256 + tid] = cw[i * 256 + tid];
    __syncthreads();

    float4* xw = xs + warp * 12 * 32;

    // stage 12 rows: t0-4 .. t0+7
    #pragma unroll
    for (int k = 0; k < 12; k++) {
        int ts = t0 - 4 + k;
        float4 v;
        if (ts < 0) {
            v = make_float4(0.f, 0.f, 0.f, 0.f);
        } else if (EMB) {
            int id = seq[b * Tt + ts];
            float4 raw = ((const float4*)(emb + (size_t)id * Cc))[lane];
            v = warp_ln(raw, sg, sb, lane);
        } else {
            v = ldbf4(XLN + ((size_t)ts * Bb + b) * Cc + lane * 4);
        }
        xw[k * 32 + lane] = v;
    }
    __syncwarp();

    // batched logits: lane j (clamped) accumulates 8 tokens
    const int j = (lane < HK) ? lane : 0;
    float acc8[8];
    {
        float cbj = __ldg(cb + j);
        #pragma unroll
        for (int tok = 0; tok < 8; tok++) acc8[tok] = cbj;
    }
    for (int c4 = 0; c4 < 32; c4++) {
        const float* wr = &ws[c4 * 4 * HK + j];
        float w0 = wr[0], w1 = wr[HK], w2 = wr[2 * HK], w3 = wr[3 * HK];
        #pragma unroll
        for (int tok = 0; tok < 8; tok++) {
            float4 xq = xw[(4 + tok) * 32 + c4];
            acc8[tok] += xq.x * w0 + xq.y * w1 + xq.z * w2 + xq.w * w3;
        }
    }

    // softmax numerators (per token); denominator computed in apply phase
    #pragma unroll
    for (int tok = 0; tok < 8; tok++) {
        if (lane < HK) lg[warp][lane] = acc8[tok];
        __syncwarp();
        if (lane < HK) {
            int hb = (lane / Kk) * Kk;
            float m = lg[warp][hb];
            #pragma unroll
            for (int k = 1; k < Kk; k++) m = fmaxf(m, lg[warp][hb + k]);
            ew[warp][tok][lane] = expf(acc8[tok] - m);
        }
        __syncwarp();
    }

    // apply + per-layer LN
    #pragma unroll
    for (int tok = 0; tok < 8; tok++) {
        float e4[Kk];
        float sden = 0.f;
        #pragma unroll
        for (int k = 0; k < Kk; k++) {
            e4[k] = ew[warp][tok][h * Kk + k];
            sden += e4[k];
        }
        float inv = 1.0f / sden;

        float4 acc = make_float4(0.f, 0.f, 0.f, 0.f);
        #pragma unroll
        for (int k = 0; k < Kk; k++) {
            float4 v = xw[(tok + k) * 32 + lane];
            float w = e4[k] * inv;
            acc.x += w * v.x; acc.y += w * v.y;
            acc.z += w * v.z; acc.w += w * v.w;
        }

        float4 r = warp_ln(acc, lng, lnb, lane);
        const size_t p = (size_t)(t0 + tok) * Bb + b;
        stbf4(XLN2 + p * Cc + lane * 4, r);
        uint32_t u = (uint32_t)f2e4m3x2(r.x, r.y)
                   | ((uint32_t)f2e4m3x2(r.z, r.w) << 16);
        *(uint32_t*)(XLN8 + p * Cc + lane * 4) = u;
    }
}

// ---------------------------------------------------------------------------
__global__ void wt_all_kernel(const float* __restrict__ fc1w,
                              const float* __restrict__ fc2w)
{
    __shared__ float tile[32][33];
    const int z = blockIdx.z;
    const int l = z >> 1;
    const bool is2 = (z & 1) != 0;
    const float* in = is2 ? fc2w + (size_t)l * Ff * Cc : fc1w + (size_t)l * Cc * Ff;
    uint8_t* out    = is2 ? g_WT2 + (size_t)l * Cc * Ff : g_WT1 + (size_t)l * Ff * Cc;
    const int Kd = is2 ? Ff : Cc;
    const int Nn = is2 ? Cc : Ff;
    const int nbx = Nn / 32;
    const int bx = blockIdx.x % nbx, by = blockIdx.x / nbx;

    int x = bx * 32 + threadIdx.x;
    int y = by * 32 + threadIdx.y;
    #pragma unroll
    for (int j = 0; j < 4; j++)
        tile[threadIdx.y + j * 8][threadIdx.x] = in[(size_t)(y + j * 8) * Nn + x];
    __syncthreads();
    int n = bx * 32 + threadIdx.y;
    int k = by * 32 + threadIdx.x;
    #pragma unroll
    for (int j = 0; j < 4; j++)
        out[(size_t)(n + j * 8) * Kd + k] =
            (uint8_t)(f2e4m3x2(tile[threadIdx.x][threadIdx.y + j * 8], 0.f) & 0xFF);
}

// ---------------------------------------------------------------------------
// Fused MLP (occ 2): CTA = 128 tokens, 256 threads, 112KB smem. (converged)
// ---------------------------------------------------------------------------
#define MLP_SMEM 114688
#define SHOFF 0u
#define SAOFF 65536u
#define SBOFF 81920u

__device__ __forceinline__ void load_b1_tile(uint32_t sbuf, const uint8_t* W1,
                                             int nt, int tid)
{
    int row = tid >> 1, j0 = (tid & 1) * 4;
    const uint8_t* src = W1 + (size_t)(nt * 128 + row) * 128;
    #pragma unroll
    for (int jj = 0; jj < 4; jj++) {
        int j = j0 + jj;
        uint32_t d = sbuf + row * 128 + (((j >> 2) ^ (row & 1)) << 6)
                   + (((j & 3) ^ ((row >> 1) & 3)) << 4);
        cp16(d, src + j * 16);
    }
}
__device__ __forceinline__ void load_b2_chunk(uint32_t sring, const uint8_t* W2,
                                              int kc, int tid)
{
    int row = tid >> 1;
    #pragma unroll
    for (int cc = 0; cc < 2; cc++) {
        int c = (tid & 1) * 2 + cc;
        uint32_t d = sring + row * 64 + ((c ^ ((row >> 1) & 3)) << 4);
        cp16(d, W2 + (size_t)row * 512 + kc * 64 + c * 16);
    }
}
__device__ __forceinline__ uint32_t hoff(int row, int col)
{
    return (uint32_t)(row * 512 + (((col >> 6) ^ (row & 7)) << 6)
         + ((((col >> 4) & 3) ^ ((row >> 1) & 3)) << 4) + (col & 15));
}

__global__ void __launch_bounds__(256, 2)
mlp_fused(const uint8_t* __restrict__ A8,
          const uint8_t* __restrict__ W1,
          const uint8_t* __restrict__ W2,
          const float* __restrict__ b1,
          const float* __restrict__ b2,
          const __nv_bfloat16* __restrict__ res,
          __nv_bfloat16* __restrict__ out,
          const float* __restrict__ sg,
          const float* __restrict__ sb)
{
    extern __shared__ __align__(1024) char sm[];
    const uint32_t S = smem_to_u32(sm);
    const uint32_t SH = S + SHOFF, SA = S + SAOFF, SB = S + SBOFF;
    const int tid = threadIdx.x, wid = tid >> 5, lane = tid & 31;
    const int bm = blockIdx.x * 128;
    const int lgrp = lane >> 3, l7 = lane & 7, g = lane >> 2, i4 = lane & 3;
    const int cA = lgrp >> 1, cB = lgrp & 1;

    const int lA = l7 + ((lgrp & 1) << 3);
    const int lB = l7 + ((lgrp >> 1) << 3);
    const int aX1 = lA & 1, aX2 = (lA >> 1) & 3, aX7 = lA & 7;
    const int bX1 = lB & 1, bX2 = (lB >> 1) & 3;
    const uint32_t aS[2] = { (uint32_t)((cA ^ aX2) << 4),
                             (uint32_t)(((2 | cA) ^ aX2) << 4) };
    const uint32_t bS[2] = { (uint32_t)((cB ^ bX2) << 4),
                             (uint32_t)(((2 | cB) ^ bX2) << 4) };

    {
        int row = tid >> 1, kb = tid & 1;
        const uint8_t* src = A8 + (size_t)(bm + row) * 128 + kb * 64;
        #pragma unroll
        for (int c = 0; c < 4; c++) {
            uint32_t d = SA + row * 128 + ((kb ^ (row & 1)) << 6)
                       + ((c ^ ((row >> 1) & 3)) << 4);
            cp16(d, src + c * 16);
        }
    }
    load_b1_tile(SB, W1, 0, tid);
    CP_COMMIT();

    const int wm = wid & 3, wn = wid >> 2;
    const uint32_t aRow = SA + wm * 4096 + lA * 128;
    const uint32_t bRowOff = wn * 8192 + lB * 128;

    #pragma unroll
    for (int nt = 0; nt < 4; nt++) {
        CP_WAIT0();
        __syncthreads();
        if (nt < 3) {
            load_b1_tile(SB + ((nt + 1) & 1) * 16384, W1, nt + 1, tid);
            CP_COMMIT();
        } else {
            load_b2_chunk(SB, W2, 0, tid);          CP_COMMIT();
            load_b2_chunk(SB + 8192, W2, 1, tid);   CP_COMMIT();
        }
        const uint32_t bRow = SB + (nt & 1) * 16384 + bRowOff;

        float acc[2][8][4] = {};
        #pragma unroll
        for (int kblk = 0; kblk < 2; kblk++) {
            const uint32_t aK = aRow + ((kblk ^ aX1) << 6);
            const uint32_t bK = bRow + ((kblk ^ bX1) << 6);
            #pragma unroll
            for (int s = 0; s < 2; s++) {
                uint32_t af[2][4], bf[4][4];
                #pragma unroll
                for (int mi = 0; mi < 2; mi++)
                    ldsm4(af[mi], aK + mi * 2048 + aS[s]);
                #pragma unroll
                for (int q = 0; q < 4; q++)
                    ldsm4(bf[q], bK + q * 2048 + bS[s]);
                #pragma unroll
                for (int mi = 0; mi < 2; mi++)
                    #pragma unroll
                    for (int ni = 0; ni < 8; ni++)
                        mma_fp8(acc[mi][ni], af[mi], &bf[ni >> 1][(ni & 1) * 2]);
            }
        }
        #pragma unroll
        for (int mi = 0; mi < 2; mi++) {
            int r = wm * 32 + mi * 16 + g;
            #pragma unroll
            for (int ni = 0; ni < 8; ni++) {
                int col = nt * 128 + wn * 64 + ni * 8 + i4 * 2;
                float bb0 = __ldg(b1 + col), bb1 = __ldg(b1 + col + 1);
                float v0 = fmaxf(acc[mi][ni][0] + bb0, 0.f);
                float v1 = fmaxf(acc[mi][ni][1] + bb1, 0.f);
                float v2 = fmaxf(acc[mi][ni][2] + bb0, 0.f);
                float v3 = fmaxf(acc[mi][ni][3] + bb1, 0.f);
                *(uint16_t*)(sm + hoff(r, col))     = f2e4m3x2(v0, v1);
                *(uint16_t*)(sm + hoff(r + 8, col)) = f2e4m3x2(v2, v3);
            }
        }
    }

    __syncthreads();
    load_b2_chunk(SB + 16384, W2, 2, tid);
    CP_COMMIT();

    const uint32_t pRow = SH + (wid * 16 + lA) * 512;

    float acc2[16][4] = {};
    #pragma unroll 2
    for (int kc = 0; kc < 8; kc++) {
        CP_WAIT2();
        __syncthreads();
        if (kc < 5) load_b2_chunk(SB + ((kc + 3) & 3) * 8192, W2, kc + 3, tid);
        CP_COMMIT();
        const uint32_t ring = SB + (kc & 3) * 8192 + lB * 64;
        const uint32_t aK = pRow + ((kc ^ aX7) << 6);

        #pragma unroll
        for (int s = 0; s < 2; s++) {
            uint32_t af[4];
            ldsm4(af, aK + aS[s]);
            const uint32_t rb = ring + bS[s];
            #pragma unroll
            for (int half = 0; half < 2; half++) {
                uint32_t bf[4][4];
                #pragma unroll
                for (int q = 0; q < 4; q++)
                    ldsm4(bf[q], rb + (half * 4 + q) * 1024);
                #pragma unroll
                for (int ni = 0; ni < 8; ni++)
                    mma_fp8(acc2[half * 8 + ni], af, &bf[ni >> 1][(ni & 1) * 2]);
            }
        }
    }

    const int rg = wid * 16 + g;
    const __nv_bfloat16* r0p = res + (size_t)(bm + rg) * Cc;
    const __nv_bfloat16* r1p = res + (size_t)(bm + rg + 8) * Cc;
    #pragma unroll
    for (int ni = 0; ni < 16; ni++) {
        int c = ni * 8 + i4 * 2;
        float bb0 = __ldg(b2 + c), bb1 = __ldg(b2 + c + 1);
        uint32_t u0 = *(const uint32_t*)(r0p + c);
        uint32_t u1 = *(const uint32_t*)(r1p + c);
        __nv_bfloat162 h0 = *reinterpret_cast<__nv_bfloat162*>(&u0);
        __nv_bfloat162 h1 = *reinterpret_cast<__nv_bfloat162*>(&u1);
        acc2[ni][0] += bb0 + __low2float(h0);  acc2[ni][1] += bb1 + __high2float(h0);
        acc2[ni][2] += bb0 + __low2float(h1);  acc2[ni][3] += bb1 + __high2float(h1);
    }
    float s1 = 0.f, s2 = 0.f;
    #pragma unroll
    for (int ni = 0; ni < 16; ni++) {
        s1 += acc2[ni][0] + acc2[ni][1];
        s2 += acc2[ni][2] + acc2[ni][3];
    }
    s1 += __shfl_xor_sync(0xffffffffu, s1, 1); s1 += __shfl_xor_sync(0xffffffffu, s1, 2);
    s2 += __shfl_xor_sync(0xffffffffu, s2, 1); s2 += __shfl_xor_sync(0xffffffffu, s2, 2);
    float m1 = s1 * (1.0f / Cc), m2 = s2 * (1.0f / Cc);
    float q1 = 0.f, q2 = 0.f;
    #pragma unroll
    for (int ni = 0; ni < 16; ni++) {
        float d0 = acc2[ni][0] - m1, d1 = acc2[ni][1] - m1;
        float d2 = acc2[ni][2] - m2, d3 = acc2[ni][3] - m2;
        q1 += d0 * d0 + d1 * d1;
        q2 += d2 * d2 + d3 * d3;
    }
    q1 += __shfl_xor_sync(0xffffffffu, q1, 1); q1 += __shfl_xor_sync(0xffffffffu, q1, 2);
    q2 += __shfl_xor_sync(0xffffffffu, q2, 1); q2 += __shfl_xor_sync(0xffffffffu, q2, 2);
    float rs1 = rsqrtf(q1 * (1.0f / Cc) + 1e-5f);
    float rs2 = rsqrtf(q2 * (1.0f / Cc) + 1e-5f);
    __nv_bfloat16* o0p = out + (size_t)(bm + rg) * Cc;
    __nv_bfloat16* o1p = out + (size_t)(bm + rg + 8) * Cc;
    #pragma unroll
    for (int ni = 0; ni < 16; ni++) {
        int c = ni * 8 + i4 * 2;
        float gg0 = __ldg(sg + c), gg1 = __ldg(sg + c + 1);
        float be0 = __ldg(sb + c), be1 = __ldg(sb + c + 1);
        __nv_bfloat162 o0 = __floats2bfloat162_rn(
            (acc2[ni][0] - m1) * rs1 * gg0 + be0,
            (acc2[ni][1] - m1) * rs1 * gg1 + be1);
        __nv_bfloat162 o1 = __floats2bfloat162_rn(
            (acc2[ni][2] - m2) * rs2 * gg0 + be0,
            (acc2[ni][3] - m2) * rs2 * gg1 + be1);
        *(uint32_t*)(o0p + c) = *(uint32_t*)&o0;
        *(uint32_t*)(o1p + c) = *(uint32_t*)&o1;
    }
}

// ---------------------------------------------------------------------------
__global__ void loss_kernel(const __nv_bfloat16* __restrict__ se,
                            const float* __restrict__ emb,
                            const int* __restrict__ pos,
                            const int* __restrict__ neg,
                            float* __restrict__ pL, float* __restrict__ pM)
{
    int warp = threadIdx.x >> 5, lane = threadIdx.x & 31;
    int i = blockIdx.x * 8 + warp;
    int b = i / Tt, t = i - b * Tt;
    int p = t * Bb + b;

    float4 e  = ldbf4(se + (size_t)p * Cc + lane * 4);
    int pid = pos[i];
    int nid = neg[i];
    float4 pv = ((const float4*)(emb + (size_t)pid * Cc))[lane];
    float4 nv = ((const float4*)(emb + (size_t)nid * Cc))[lane];
    float dp = e.x*pv.x + e.y*pv.y + e.z*pv.z + e.w*pv.w;
    float dn = e.x*nv.x + e.y*nv.y + e.z*nv.z + e.w*nv.w;
    #pragma unroll
    for (int o = 16; o; o >>= 1) {
        dp += __shfl_xor_sync(0xffffffffu, dp, o);
        dn += __shfl_xor_sync(0xffffffffu, dn, o);
    }

    __shared__ float sL[8], sM[8];
    if (lane == 0) {
        float sp = 1.0f / (1.0f + expf(-dp));
        float sn = 1.0f / (1.0f + expf(-dn));
        float val = -logf(sp + 1e-24f) - logf(1.0f - sn + 1e-24f);
        float m = (pid != 0) ? 1.0f : 0.0f;
        sL[warp] = val * m;
        sM[warp] = m;
    }
    __syncthreads();
    if (threadIdx.x == 0) {
        float a = 0.f, mm = 0.f;
        #pragma unroll
        for (int w = 0; w < 8; w++) { a += sL[w]; mm += sM[w]; }
        pL[blockIdx.x] = a;
        pM[blockIdx.x] = mm;
    }
}

__global__ void reduce_kernel(const float* __restrict__ pL,
                              const float* __restrict__ pM,
                              float* __restrict__ out)
{
    __shared__ double sL[1024], sM[1024];
    double a = 0.0, m = 0.0;
    for (int i = threadIdx.x; i < NPART; i += 1024) { a += pL[i]; m += pM[i]; }
    sL[threadIdx.x] = a; sM[threadIdx.x] = m;
    __syncthreads();
    for (int s = 512; s; s >>= 1) {
        if (threadIdx.x < s) {
            sL[threadIdx.x] += sL[threadIdx.x + s];
            sM[threadIdx.x] += sM[threadIdx.x + s];
        }
        __syncthreads();
    }
    if (threadIdx.x == 0) out[0] = (float)(sL[0] / sM[0]);
}

// ---------------------------------------------------------------------------
extern "C" void kernel_launch(void* const* d_in, const int* in_sizes, int n_in,
                              void* d_out, int out_size)
{
    const float* item_emb = (const float*)d_in[0];
    const float* conv_w   = (const float*)d_in[1];
    const float* conv_b   = (const float*)d_in[2];
    const float* ln_g     = (const float*)d_in[3];
    const float* ln_b     = (const float*)d_in[4];
    const float* fc1_w    = (const float*)d_in[5];
    const float* fc1_b    = (const float*)d_in[6];
    const float* fc2_w    = (const float*)d_in[7];
    const float* fc2_b    = (const float*)d_in[8];
    const float* sln_g    = (const float*)d_in[9];
    const float* sln_b    = (const float*)d_in[10];
    const int*   seq      = (const int*)d_in[11];
    const int*   pos      = (const int*)d_in[12];
    const int*   neg      = (const int*)d_in[13];

    __nv_bfloat16 *XLN, *XLN2;
    float *pL, *pM;
    uint8_t *XLN8, *WT1, *WT2;
    cudaGetSymbolAddress((void**)&XLN,  g_XLN);
    cudaGetSymbolAddress((void**)&XLN2, g_XLN2);
    cudaGetSymbolAddress((void**)&XLN8, g_XLN8);
    cudaGetSymbolAddress((void**)&WT1,  g_WT1);
    cudaGetSymbolAddress((void**)&WT2,  g_WT2);
    cudaGetSymbolAddress((void**)&pL,   g_pL);
    cudaGetSymbolAddress((void**)&pM,   g_pM);

    cudaFuncSetAttribute(mlp_fused,
        cudaFuncAttributeMaxDynamicSharedMemorySize, MLP_SMEM);
    cudaFuncSetAttribute(conv_ln_kernel<true>,
        cudaFuncAttributeMaxDynamicSharedMemorySize, CONV_SMEM);
    cudaFuncSetAttribute(conv_ln_kernel<false>,
        cudaFuncAttributeMaxDynamicSharedMemorySize, CONV_SMEM);

    const int gr8 = BTt / 8;
    dim3 blk(256);
    dim3 cgrid(Tt / 8, Bb / 8);

    wt_all_kernel<<<dim3(64, 1, Ll * 2), dim3(32, 8)>>>(fc1_w, fc2_w);

    // layer 0: conv consumes LN(emb[seq]) directly
    conv_ln_kernel<true><<<cgrid, blk, CONV_SMEM>>>(
        nullptr, item_emb, seq, sln_g, sln_b,
        conv_w, conv_b, ln_g, ln_b, XLN2, XLN8);
    mlp_fused<<<BTt / 128, 256, MLP_SMEM>>>(
        XLN8, WT1, WT2, fc1_b, fc2_b, XLN2, XLN, sln_g, sln_b);

    // layer 1
    conv_ln_kernel<false><<<cgrid, blk, CONV_SMEM>>>(
        XLN, nullptr, nullptr, nullptr, nullptr,
        conv_w + (size_t)Cc * HK, conv_b + HK,
        ln_g + Cc, ln_b + Cc, XLN2, XLN8);
    mlp_fused<<<BTt / 128, 256, MLP_SMEM>>>(
        XLN8, WT1 + (size_t)Ff * Cc, WT2 + (size_t)Cc * Ff,
        fc1_b + Ff, fc2_b + Cc, XLN2, XLN, sln_g, sln_b);

    loss_kernel<<<gr8, blk>>>(XLN, item_emb, pos, neg, pL, pM);
    reduce_kernel<<<1, 1024>>>(pL, pM, (float*)d_out);
}